// round 5
// baseline (speedup 1.0000x reference)
#include <cuda_runtime.h>
#include <math.h>

typedef unsigned long long u64;

// ---- problem dims ----
#define NB      32
#define NUMPTS  2048
#define PN      1024
#define KK      16
#define CIN     64
#define CHALF   64
#define CMID    32
#define CCAT    96
#define COUT    128
#define TILEP   8
#define FCS     100
#define BNI     0.9999950000374996f

// scratch: lifted features fts_l (N, NUM_PTS, 64)
__device__ float g_ftsl[NB * NUMPTS * CHALF];

__device__ __forceinline__ float eluf(float x) {
    return x > 0.0f ? x : expm1f(x);
}
__device__ __forceinline__ u64 fma2(u64 a, u64 b, u64 c) {
    u64 d; asm("fma.rn.f32x2 %0,%1,%2,%3;" : "=l"(d) : "l"(a), "l"(b), "l"(c)); return d;
}
__device__ __forceinline__ u64 dup2(float x) {
    u64 d; asm("mov.b64 %0,{%1,%1};" : "=l"(d) : "f"(x)); return d;
}
__device__ __forceinline__ float2 unpk(u64 v) {
    float2 r; asm("mov.b64 {%0,%1},%2;" : "=f"(r.x), "=f"(r.y) : "l"(v)); return r;
}

// ============================================================================
// Kernel A: fts_l = d0_g * (elu(fts @ d0_W + d0_b) * BNI) + d0_be
// ============================================================================
__global__ void __launch_bounds__(256) dense0_kernel(
    const float* __restrict__ fts, const float* __restrict__ W,
    const float* __restrict__ b,   const float* __restrict__ g,
    const float* __restrict__ be)
{
    __shared__ float Ws[64 * 64];
    __shared__ float xs[16 * 64];
    const int t = threadIdx.x;
    const size_t row0 = (size_t)blockIdx.x * 16;

#pragma unroll
    for (int u = 0; u < 16; u++) Ws[t + 256 * u] = W[t + 256 * u];
    ((float4*)xs)[t] = ((const float4*)(fts + row0 * 64))[t];
    __syncthreads();

    const int r  = t >> 4;
    const int cb = (t & 15) * 4;
    u64 a0 = 0ull, a1 = 0ull;
#pragma unroll 8
    for (int k = 0; k < 64; k++) {
        u64 xd = dup2(xs[r * 64 + k]);
        ulonglong2 w = *(const ulonglong2*)&Ws[k * 64 + cb];
        a0 = fma2(xd, w.x, a0);
        a1 = fma2(xd, w.y, a1);
    }
    float2 f0 = unpk(a0), f1 = unpk(a1);
    float4 b4 = *(const float4*)&b[cb];
    float4 g4 = *(const float4*)&g[cb];
    float4 e4 = *(const float4*)&be[cb];
    float4 o;
    o.x = g4.x * (eluf(f0.x + b4.x) * BNI) + e4.x;
    o.y = g4.y * (eluf(f0.y + b4.y) * BNI) + e4.y;
    o.z = g4.z * (eluf(f1.x + b4.z) * BNI) + e4.z;
    o.w = g4.w * (eluf(f1.y + b4.w) * BNI) + e4.w;
    *(float4*)&g_ftsl[(row0 + r) * 64 + cb] = o;
}

// ============================================================================
// Kernel B: fused XConv. TILE_P=8, 256 threads, 3 CTAs/SM (85-reg cap).
// Structure identical to the 793us version; C/D unroll reduced to 2 to fit
// the register budget without spills.
// smem: 18720 floats = 74880 B per CTA (3 CTAs = 224.6KB <= 228KB)
// ============================================================================
#define SM_FLOATS 18720
#define SMEM_B    (SM_FLOATS * 4)

__global__ void __launch_bounds__(256, 3) xconv_kernel(
    const float* __restrict__ rep_pts, const float* __restrict__ pts,
    const int*   __restrict__ pts_idx,
    const float* __restrict__ d1W, const float* __restrict__ d1b,
    const float* __restrict__ d1g, const float* __restrict__ d1be,
    const float* __restrict__ d2W, const float* __restrict__ d2b,
    const float* __restrict__ d2g, const float* __restrict__ d2be,
    const float* __restrict__ xcW,  const float* __restrict__ xcb,
    const float* __restrict__ xd1W, const float* __restrict__ xd1b,
    const float* __restrict__ xd2W, const float* __restrict__ xd2b,
    const float* __restrict__ dwW,  const float* __restrict__ dwb,
    const float* __restrict__ pwW,  const float* __restrict__ pwb,
    const float* __restrict__ endg, const float* __restrict__ endbe,
    float* __restrict__ out)
{
    extern __shared__ float sm[];
    float* PT   = sm;            // [48][8]
    float* XA   = sm + 384;      // [256][8]
    float* XB   = sm + 2432;     // [256][8]
    float* H    = sm + 384;      // [32][128]  (E phase only)
    float* FC   = sm + 4480;     // [8][16][FCS]
    int*   SIDX = (int*)(sm + 17280);
    float* SD1W = sm + 17408; float* SD1B  = sm + 17504;
    float* SD1G = sm + 17536; float* SD1BE = sm + 17568;
    float* SD2W = sm + 17600; float* SD2B  = sm + 18624;
    float* SD2G = sm + 18656; float* SD2BE = sm + 18688;

    const int t   = threadIdx.x;
    const int gp0 = blockIdx.x * TILEP;
    const int n   = gp0 >> 10;

    // ---- load small weights + neighbor indices ----
    for (int u = t; u < 96 + 1024; u += 256) {
        if (u < 96) SD1W[u] = d1W[u];
        else        SD2W[u - 96] = d2W[u - 96];
    }
    if (t < 32) {
        SD1B[t] = d1b[t]; SD1G[t] = d1g[t]; SD1BE[t] = d1be[t];
        SD2B[t] = d2b[t]; SD2G[t] = d2g[t]; SD2BE[t] = d2be[t];
    }
    if (t < 128) SIDX[t] = pts_idx[(size_t)gp0 * 16 + t];
    __syncthreads();

    // ---- gather coords (transposed, centered) + gather lifted features ----
    if (t < 128) {
        int i = t >> 4, k = t & 15;
        int gi = SIDX[t];
        const float* pp = pts + ((size_t)n * NUMPTS + gi) * 3;
        const float* rp = rep_pts + (size_t)(gp0 + i) * 3;
        PT[( 0 + k) * 8 + i] = pp[0] - rp[0];
        PT[(16 + k) * 8 + i] = pp[1] - rp[1];
        PT[(32 + k) * 8 + i] = pp[2] - rp[2];
    }
    {
        int row = t >> 1, half = t & 1;          // 128 rows x 2 halves
        int gi = SIDX[row];
        const float4* src = (const float4*)(g_ftsl + ((size_t)n * NUMPTS + gi) * 64 + half * 32);
        float4* dst = (float4*)&FC[row * FCS + 32 + half * 32];
#pragma unroll
        for (int u = 0; u < 8; u++) dst[u] = src[u];
    }
    __syncthreads();

    // ---- E1: dense1 (3 -> 32) into H[c][row] ----
    {
        const int row = t & 127, hc = t >> 7;
        const int i = row >> 4, k = row & 15;
        float px = PT[k * 8 + i];
        float py = PT[(16 + k) * 8 + i];
        float pz = PT[(32 + k) * 8 + i];
#pragma unroll
        for (int u = 0; u < 16; u++) {
            int c = hc * 16 + u;
            float v = fmaf(px, SD1W[c], fmaf(py, SD1W[32 + c],
                      fmaf(pz, SD1W[64 + c], SD1B[c])));
            H[c * 128 + row] = SD1G[c] * (eluf(v) * BNI) + SD1BE[c];
        }
    }
    __syncthreads();

    // ---- E2: dense2 (32 -> 32) from H into FC[:, 0:32] ----
    {
        const int row = t & 127, hc = t >> 7;
        float acc[16];
#pragma unroll
        for (int u = 0; u < 16; u++) acc[u] = SD2B[hc * 16 + u];
#pragma unroll 2
        for (int c = 0; c < 32; c++) {
            float hv = H[c * 128 + row];
            const float4* w4 = (const float4*)&SD2W[c * 32 + hc * 16];
#pragma unroll
            for (int q4 = 0; q4 < 4; q4++) {
                float4 w = w4[q4];
                acc[q4 * 4 + 0] += hv * w.x; acc[q4 * 4 + 1] += hv * w.y;
                acc[q4 * 4 + 2] += hv * w.z; acc[q4 * 4 + 3] += hv * w.w;
            }
        }
#pragma unroll
        for (int u = 0; u < 16; u++) {
            int c2 = hc * 16 + u;
            FC[row * FCS + c2] = SD2G[c2] * (eluf(acc[u]) * BNI) + SD2BE[c2];
        }
    }
    __syncthreads();   // H region about to be overwritten by phase B

    // ---- Phase B: X0[q] = elu(sum_48 pls*xcW[q]) -> XA[q][i], packed pairs ----
    {
        const int q = t;
        u64 acc[4] = {0ull, 0ull, 0ull, 0ull};
        const float4* w4p = (const float4*)(xcW + q * 48);
#pragma unroll 2
        for (int k4 = 0; k4 < 12; k4++) {
            float4 w = w4p[k4];
            float wv[4] = {w.x, w.y, w.z, w.w};
#pragma unroll
            for (int u = 0; u < 4; u++) {
                u64 wd = dup2(wv[u]);
                int k = k4 * 4 + u;
                ulonglong2 a0 = *(const ulonglong2*)&PT[k * 8];
                ulonglong2 a1 = *(const ulonglong2*)&PT[k * 8 + 4];
                acc[0] = fma2(a0.x, wd, acc[0]);
                acc[1] = fma2(a0.y, wd, acc[1]);
                acc[2] = fma2(a1.x, wd, acc[2]);
                acc[3] = fma2(a1.y, wd, acc[3]);
            }
        }
        float b = xcb[q];
        float2 f0 = unpk(acc[0]), f1 = unpk(acc[1]);
        float2 f2 = unpk(acc[2]), f3 = unpk(acc[3]);
        float4 o0, o1;
        o0.x = eluf(f0.x + b); o0.y = eluf(f0.y + b);
        o0.z = eluf(f1.x + b); o0.w = eluf(f1.y + b);
        o1.x = eluf(f2.x + b); o1.y = eluf(f2.y + b);
        o1.z = eluf(f3.x + b); o1.w = eluf(f3.y + b);
        *(float4*)&XA[q * 8]     = o0;
        *(float4*)&XA[q * 8 + 4] = o1;
    }
    __syncthreads();

    // ---- Phase C: X1 = elu(X0 @ xd1W + b) -> XB[q][i], packed pairs ----
    {
        const int q = t;
        u64 acc[4] = {0ull, 0ull, 0ull, 0ull};
#pragma unroll 2
        for (int j = 0; j < 256; j++) {
            u64 wd = dup2(__ldg(&xd1W[j * 256 + q]));
            ulonglong2 a0 = *(const ulonglong2*)&XA[j * 8];
            ulonglong2 a1 = *(const ulonglong2*)&XA[j * 8 + 4];
            acc[0] = fma2(a0.x, wd, acc[0]);
            acc[1] = fma2(a0.y, wd, acc[1]);
            acc[2] = fma2(a1.x, wd, acc[2]);
            acc[3] = fma2(a1.y, wd, acc[3]);
        }
        float b = xd1b[q];
        float2 f0 = unpk(acc[0]), f1 = unpk(acc[1]);
        float2 f2 = unpk(acc[2]), f3 = unpk(acc[3]);
        float4 o0, o1;
        o0.x = eluf(f0.x + b); o0.y = eluf(f0.y + b);
        o0.z = eluf(f1.x + b); o0.w = eluf(f1.y + b);
        o1.x = eluf(f2.x + b); o1.y = eluf(f2.y + b);
        o1.z = eluf(f3.x + b); o1.w = eluf(f3.y + b);
        *(float4*)&XB[q * 8]     = o0;
        *(float4*)&XB[q * 8 + 4] = o1;
    }
    __syncthreads();

    // ---- Phase D: X2 = X1 @ xd2W + b -> XA as [8][256], packed pairs ----
    {
        const int q = t;
        u64 acc[4] = {0ull, 0ull, 0ull, 0ull};
#pragma unroll 2
        for (int j = 0; j < 256; j++) {
            u64 wd = dup2(__ldg(&xd2W[j * 256 + q]));
            ulonglong2 a0 = *(const ulonglong2*)&XB[j * 8];
            ulonglong2 a1 = *(const ulonglong2*)&XB[j * 8 + 4];
            acc[0] = fma2(a0.x, wd, acc[0]);
            acc[1] = fma2(a0.y, wd, acc[1]);
            acc[2] = fma2(a1.x, wd, acc[2]);
            acc[3] = fma2(a1.y, wd, acc[3]);
        }
        float b = xd2b[q];
        float2 f0 = unpk(acc[0]), f1 = unpk(acc[1]);
        float2 f2 = unpk(acc[2]), f3 = unpk(acc[3]);
        XA[0 * 256 + q] = f0.x + b;  XA[1 * 256 + q] = f0.y + b;
        XA[2 * 256 + q] = f1.x + b;  XA[3 * 256 + q] = f1.y + b;
        XA[4 * 256 + q] = f2.x + b;  XA[5 * 256 + q] = f2.y + b;
        XA[6 * 256 + q] = f3.x + b;  XA[7 * 256 + q] = f3.y + b;
    }
    __syncthreads();

    // ---- Phase F: fts_X = X2(16x16) @ FC(16x96), in place in FC ----
    {
        const int i = t >> 5, lane = t & 31;
        const float* X2 = &XA[i * 256];
#pragma unroll
        for (int u = 0; u < 3; u++) {
            int c = lane + 32 * u;
            float f[16];
#pragma unroll
            for (int cc = 0; cc < 16; cc++) f[cc] = FC[(i * 16 + cc) * FCS + c];
#pragma unroll
            for (int r = 0; r < 16; r++) {
                float acc = 0.f;
                const float4* xr = (const float4*)&X2[r * 16];
#pragma unroll
                for (int c4 = 0; c4 < 4; c4++) {
                    float4 xv = xr[c4];
                    acc += xv.x * f[c4 * 4] + xv.y * f[c4 * 4 + 1]
                         + xv.z * f[c4 * 4 + 2] + xv.w * f[c4 * 4 + 3];
                }
                FC[(i * 16 + r) * FCS + c] = acc;
            }
        }
    }
    __syncthreads();

    // ---- Phase G1: depthwise dw[cm] = sum_k ftsX[k][c]*dwW[c][m][k] + dwb ----
    float* DWS = XB;   // reuse as [8][256], first 192 valid
    {
        const int i = t >> 5, lane = t & 31;
#pragma unroll
        for (int u = 0; u < 6; u++) {
            int cm = lane + 32 * u;         // 0..191
            int c = cm >> 1, m = cm & 1;
            float w[16];
            const float4* wp = (const float4*)(dwW + c * 32 + m * 16);
            *(float4*)&w[0]  = wp[0]; *(float4*)&w[4]  = wp[1];
            *(float4*)&w[8]  = wp[2]; *(float4*)&w[12] = wp[3];
            float acc = dwb[cm];
#pragma unroll
            for (int k = 0; k < 16; k++) acc += FC[(i * 16 + k) * FCS + c] * w[k];
            DWS[i * 256 + cm] = acc;
        }
    }
    __syncthreads();

    // ---- Phase G2: out = end_g*(elu(dw @ pwW + pwb)*BNI) + end_be ----
    {
        const int i = t >> 5, lane = t & 31;
        const int ob = lane * 4;
        ulonglong2 bi = *(const ulonglong2*)&pwb[ob];
        u64 acc0 = bi.x, acc1 = bi.y;
#pragma unroll 2
        for (int j = 0; j < 192; j++) {
            u64 vd = dup2(DWS[i * 256 + j]);
            ulonglong2 w = *(const ulonglong2*)&pwW[j * 128 + ob];
            acc0 = fma2(vd, w.x, acc0);
            acc1 = fma2(vd, w.y, acc1);
        }
        float2 f0 = unpk(acc0), f1 = unpk(acc1);
        float4 g4 = *(const float4*)&endg[ob];
        float4 e4 = *(const float4*)&endbe[ob];
        float4 o;
        o.x = g4.x * (eluf(f0.x) * BNI) + e4.x;
        o.y = g4.y * (eluf(f0.y) * BNI) + e4.y;
        o.z = g4.z * (eluf(f1.x) * BNI) + e4.z;
        o.w = g4.w * (eluf(f1.y) * BNI) + e4.w;
        *(float4*)&out[(size_t)(gp0 + i) * 128 + ob] = o;
    }
}

// ============================================================================
extern "C" void kernel_launch(void* const* d_in, const int* in_sizes, int n_in,
                              void* d_out, int out_size)
{
    const float* rep_pts = (const float*)d_in[0];
    const float* pts     = (const float*)d_in[1];
    const float* fts     = (const float*)d_in[2];
    const int*   pts_idx = (const int*)d_in[3];
    const float* d0W  = (const float*)d_in[4];
    const float* d0b  = (const float*)d_in[5];
    const float* d0g  = (const float*)d_in[6];
    const float* d0be = (const float*)d_in[7];
    const float* d1W  = (const float*)d_in[8];
    const float* d1b  = (const float*)d_in[9];
    const float* d1g  = (const float*)d_in[10];
    const float* d1be = (const float*)d_in[11];
    const float* d2W  = (const float*)d_in[12];
    const float* d2b  = (const float*)d_in[13];
    const float* d2g  = (const float*)d_in[14];
    const float* d2be = (const float*)d_in[15];
    const float* xcW  = (const float*)d_in[16];
    const float* xcb  = (const float*)d_in[17];
    const float* xd1W = (const float*)d_in[18];
    const float* xd1b = (const float*)d_in[19];
    const float* xd2W = (const float*)d_in[20];
    const float* xd2b = (const float*)d_in[21];
    const float* dwW  = (const float*)d_in[22];
    const float* dwb  = (const float*)d_in[23];
    const float* pwW  = (const float*)d_in[24];
    const float* pwb  = (const float*)d_in[25];
    const float* endg = (const float*)d_in[26];
    const float* endbe= (const float*)d_in[27];
    float* out = (float*)d_out;

    dense0_kernel<<<4096, 256>>>(fts, d0W, d0b, d0g, d0be);

    cudaFuncSetAttribute(xconv_kernel,
                         cudaFuncAttributeMaxDynamicSharedMemorySize, SMEM_B);
    xconv_kernel<<<32768 / TILEP, 256, SMEM_B>>>(
        rep_pts, pts, pts_idx,
        d1W, d1b, d1g, d1be, d2W, d2b, d2g, d2be,
        xcW, xcb, xd1W, xd1b, xd2W, xd2b,
        dwW, dwb, pwW, pwb, endg, endbe, out);
}

// round 6
// speedup vs baseline: 1.2207x; 1.2207x over previous
#include <cuda_runtime.h>
#include <math.h>

typedef unsigned long long u64;

// ---- problem dims ----
#define NB      32
#define NUMPTS  2048
#define PN      1024
#define KK      16
#define CIN     64
#define CHALF   64
#define CMID    32
#define CCAT    96
#define COUT    128
#define TILEP   8
#define FCS     100
#define BNI     0.9999950000374996f

// scratch: lifted features fts_l (N, NUM_PTS, 64)
__device__ float g_ftsl[NB * NUMPTS * CHALF];

__device__ __forceinline__ float eluf(float x) {
    return x > 0.0f ? x : expm1f(x);
}
__device__ __forceinline__ u64 fma2(u64 a, u64 b, u64 c) {
    u64 d; asm("fma.rn.f32x2 %0,%1,%2,%3;" : "=l"(d) : "l"(a), "l"(b), "l"(c)); return d;
}
__device__ __forceinline__ u64 dup2(float x) {
    u64 d; asm("mov.b64 %0,{%1,%1};" : "=l"(d) : "f"(x)); return d;
}
__device__ __forceinline__ float2 unpk(u64 v) {
    float2 r; asm("mov.b64 {%0,%1},%2;" : "=f"(r.x), "=f"(r.y) : "l"(v)); return r;
}

// ============================================================================
// Kernel A: fts_l = d0_g * (elu(fts @ d0_W + d0_b) * BNI) + d0_be
// ============================================================================
__global__ void __launch_bounds__(256) dense0_kernel(
    const float* __restrict__ fts, const float* __restrict__ W,
    const float* __restrict__ b,   const float* __restrict__ g,
    const float* __restrict__ be)
{
    __shared__ float Ws[64 * 64];
    __shared__ float xs[16 * 64];
    const int t = threadIdx.x;
    const size_t row0 = (size_t)blockIdx.x * 16;

#pragma unroll
    for (int u = 0; u < 16; u++) Ws[t + 256 * u] = W[t + 256 * u];
    ((float4*)xs)[t] = ((const float4*)(fts + row0 * 64))[t];
    __syncthreads();

    const int r  = t >> 4;
    const int cb = (t & 15) * 4;
    u64 a0 = 0ull, a1 = 0ull;
#pragma unroll 8
    for (int k = 0; k < 64; k++) {
        u64 xd = dup2(xs[r * 64 + k]);
        ulonglong2 w = *(const ulonglong2*)&Ws[k * 64 + cb];
        a0 = fma2(xd, w.x, a0);
        a1 = fma2(xd, w.y, a1);
    }
    float2 f0 = unpk(a0), f1 = unpk(a1);
    float4 b4 = *(const float4*)&b[cb];
    float4 g4 = *(const float4*)&g[cb];
    float4 e4 = *(const float4*)&be[cb];
    float4 o;
    o.x = g4.x * (eluf(f0.x + b4.x) * BNI) + e4.x;
    o.y = g4.y * (eluf(f0.y + b4.y) * BNI) + e4.y;
    o.z = g4.z * (eluf(f1.x + b4.z) * BNI) + e4.z;
    o.w = g4.w * (eluf(f1.y + b4.w) * BNI) + e4.w;
    *(float4*)&g_ftsl[(row0 + r) * 64 + cb] = o;
}

// ============================================================================
// Kernel B: fused XConv. TILE_P=8, 256 threads, 2 CTAs/SM.
// R4 structure; phases C/D use front-batched 8-weight register prefetch
// (MLP=8 on the L2 weight stream), G2 uses 4-wide LDG.128 prefetch.
// smem: 18720 floats = 74880 B per CTA
// ============================================================================
#define SM_FLOATS 18720
#define SMEM_B    (SM_FLOATS * 4)

__global__ void __launch_bounds__(256, 2) xconv_kernel(
    const float* __restrict__ rep_pts, const float* __restrict__ pts,
    const int*   __restrict__ pts_idx,
    const float* __restrict__ d1W, const float* __restrict__ d1b,
    const float* __restrict__ d1g, const float* __restrict__ d1be,
    const float* __restrict__ d2W, const float* __restrict__ d2b,
    const float* __restrict__ d2g, const float* __restrict__ d2be,
    const float* __restrict__ xcW,  const float* __restrict__ xcb,
    const float* __restrict__ xd1W, const float* __restrict__ xd1b,
    const float* __restrict__ xd2W, const float* __restrict__ xd2b,
    const float* __restrict__ dwW,  const float* __restrict__ dwb,
    const float* __restrict__ pwW,  const float* __restrict__ pwb,
    const float* __restrict__ endg, const float* __restrict__ endbe,
    float* __restrict__ out)
{
    extern __shared__ float sm[];
    float* PT   = sm;            // [48][8]
    float* XA   = sm + 384;      // [256][8]
    float* XB   = sm + 2432;     // [256][8]
    float* H    = sm + 384;      // [32][128]  (E phase only)
    float* FC   = sm + 4480;     // [8][16][FCS]
    int*   SIDX = (int*)(sm + 17280);
    float* SD1W = sm + 17408; float* SD1B  = sm + 17504;
    float* SD1G = sm + 17536; float* SD1BE = sm + 17568;
    float* SD2W = sm + 17600; float* SD2B  = sm + 18624;
    float* SD2G = sm + 18656; float* SD2BE = sm + 18688;

    const int t   = threadIdx.x;
    const int gp0 = blockIdx.x * TILEP;
    const int n   = gp0 >> 10;

    // ---- load small weights + neighbor indices ----
    for (int u = t; u < 96 + 1024; u += 256) {
        if (u < 96) SD1W[u] = d1W[u];
        else        SD2W[u - 96] = d2W[u - 96];
    }
    if (t < 32) {
        SD1B[t] = d1b[t]; SD1G[t] = d1g[t]; SD1BE[t] = d1be[t];
        SD2B[t] = d2b[t]; SD2G[t] = d2g[t]; SD2BE[t] = d2be[t];
    }
    if (t < 128) SIDX[t] = pts_idx[(size_t)gp0 * 16 + t];
    __syncthreads();

    // ---- gather coords (transposed, centered) + gather lifted features ----
    if (t < 128) {
        int i = t >> 4, k = t & 15;
        int gi = SIDX[t];
        const float* pp = pts + ((size_t)n * NUMPTS + gi) * 3;
        const float* rp = rep_pts + (size_t)(gp0 + i) * 3;
        PT[( 0 + k) * 8 + i] = pp[0] - rp[0];
        PT[(16 + k) * 8 + i] = pp[1] - rp[1];
        PT[(32 + k) * 8 + i] = pp[2] - rp[2];
    }
    {
        int row = t >> 1, half = t & 1;          // 128 rows x 2 halves
        int gi = SIDX[row];
        const float4* src = (const float4*)(g_ftsl + ((size_t)n * NUMPTS + gi) * 64 + half * 32);
        float4* dst = (float4*)&FC[row * FCS + 32 + half * 32];
#pragma unroll
        for (int u = 0; u < 8; u++) dst[u] = src[u];
    }
    __syncthreads();

    // ---- E1: dense1 (3 -> 32) into H[c][row] ----
    {
        const int row = t & 127, hc = t >> 7;
        const int i = row >> 4, k = row & 15;
        float px = PT[k * 8 + i];
        float py = PT[(16 + k) * 8 + i];
        float pz = PT[(32 + k) * 8 + i];
#pragma unroll
        for (int u = 0; u < 16; u++) {
            int c = hc * 16 + u;
            float v = fmaf(px, SD1W[c], fmaf(py, SD1W[32 + c],
                      fmaf(pz, SD1W[64 + c], SD1B[c])));
            H[c * 128 + row] = SD1G[c] * (eluf(v) * BNI) + SD1BE[c];
        }
    }
    __syncthreads();

    // ---- E2: dense2 (32 -> 32) from H into FC[:, 0:32] ----
    {
        const int row = t & 127, hc = t >> 7;
        float acc[16];
#pragma unroll
        for (int u = 0; u < 16; u++) acc[u] = SD2B[hc * 16 + u];
#pragma unroll 4
        for (int c = 0; c < 32; c++) {
            float hv = H[c * 128 + row];
            const float4* w4 = (const float4*)&SD2W[c * 32 + hc * 16];
#pragma unroll
            for (int q4 = 0; q4 < 4; q4++) {
                float4 w = w4[q4];
                acc[q4 * 4 + 0] += hv * w.x; acc[q4 * 4 + 1] += hv * w.y;
                acc[q4 * 4 + 2] += hv * w.z; acc[q4 * 4 + 3] += hv * w.w;
            }
        }
#pragma unroll
        for (int u = 0; u < 16; u++) {
            int c2 = hc * 16 + u;
            FC[row * FCS + c2] = SD2G[c2] * (eluf(acc[u]) * BNI) + SD2BE[c2];
        }
    }
    __syncthreads();   // H region about to be overwritten by phase B

    // ---- Phase B: X0[q] = elu(sum_48 pls*xcW[q]) -> XA[q][i], packed pairs ----
    {
        const int q = t;
        u64 acc[4] = {0ull, 0ull, 0ull, 0ull};
        const float4* w4p = (const float4*)(xcW + q * 48);
#pragma unroll 4
        for (int k4 = 0; k4 < 12; k4++) {
            float4 w = w4p[k4];
            float wv[4] = {w.x, w.y, w.z, w.w};
#pragma unroll
            for (int u = 0; u < 4; u++) {
                u64 wd = dup2(wv[u]);
                int k = k4 * 4 + u;
                ulonglong2 a0 = *(const ulonglong2*)&PT[k * 8];
                ulonglong2 a1 = *(const ulonglong2*)&PT[k * 8 + 4];
                acc[0] = fma2(a0.x, wd, acc[0]);
                acc[1] = fma2(a0.y, wd, acc[1]);
                acc[2] = fma2(a1.x, wd, acc[2]);
                acc[3] = fma2(a1.y, wd, acc[3]);
            }
        }
        float b = xcb[q];
        float2 f0 = unpk(acc[0]), f1 = unpk(acc[1]);
        float2 f2 = unpk(acc[2]), f3 = unpk(acc[3]);
        float4 o0, o1;
        o0.x = eluf(f0.x + b); o0.y = eluf(f0.y + b);
        o0.z = eluf(f1.x + b); o0.w = eluf(f1.y + b);
        o1.x = eluf(f2.x + b); o1.y = eluf(f2.y + b);
        o1.z = eluf(f3.x + b); o1.w = eluf(f3.y + b);
        *(float4*)&XA[q * 8]     = o0;
        *(float4*)&XA[q * 8 + 4] = o1;
    }
    __syncthreads();

    // ---- Phase C: X1 = elu(X0 @ xd1W + b), 8-weight register prefetch ----
    {
        const int q = t;
        u64 acc[4] = {0ull, 0ull, 0ull, 0ull};
        const float* wp = xd1W + q;
#pragma unroll 1
        for (int jt = 0; jt < 256; jt += 8) {
            float w[8];
#pragma unroll
            for (int u = 0; u < 8; u++)
                w[u] = __ldg(&wp[(jt + u) * 256]);
#pragma unroll
            for (int u = 0; u < 8; u++) {
                u64 wd = dup2(w[u]);
                ulonglong2 a0 = *(const ulonglong2*)&XA[(jt + u) * 8];
                ulonglong2 a1 = *(const ulonglong2*)&XA[(jt + u) * 8 + 4];
                acc[0] = fma2(a0.x, wd, acc[0]);
                acc[1] = fma2(a0.y, wd, acc[1]);
                acc[2] = fma2(a1.x, wd, acc[2]);
                acc[3] = fma2(a1.y, wd, acc[3]);
            }
        }
        float b = xd1b[q];
        float2 f0 = unpk(acc[0]), f1 = unpk(acc[1]);
        float2 f2 = unpk(acc[2]), f3 = unpk(acc[3]);
        float4 o0, o1;
        o0.x = eluf(f0.x + b); o0.y = eluf(f0.y + b);
        o0.z = eluf(f1.x + b); o0.w = eluf(f1.y + b);
        o1.x = eluf(f2.x + b); o1.y = eluf(f2.y + b);
        o1.z = eluf(f3.x + b); o1.w = eluf(f3.y + b);
        *(float4*)&XB[q * 8]     = o0;
        *(float4*)&XB[q * 8 + 4] = o1;
    }
    __syncthreads();

    // ---- Phase D: X2 = X1 @ xd2W + b -> XA as [8][256], same prefetch ----
    {
        const int q = t;
        u64 acc[4] = {0ull, 0ull, 0ull, 0ull};
        const float* wp = xd2W + q;
#pragma unroll 1
        for (int jt = 0; jt < 256; jt += 8) {
            float w[8];
#pragma unroll
            for (int u = 0; u < 8; u++)
                w[u] = __ldg(&wp[(jt + u) * 256]);
#pragma unroll
            for (int u = 0; u < 8; u++) {
                u64 wd = dup2(w[u]);
                ulonglong2 a0 = *(const ulonglong2*)&XB[(jt + u) * 8];
                ulonglong2 a1 = *(const ulonglong2*)&XB[(jt + u) * 8 + 4];
                acc[0] = fma2(a0.x, wd, acc[0]);
                acc[1] = fma2(a0.y, wd, acc[1]);
                acc[2] = fma2(a1.x, wd, acc[2]);
                acc[3] = fma2(a1.y, wd, acc[3]);
            }
        }
        float b = xd2b[q];
        float2 f0 = unpk(acc[0]), f1 = unpk(acc[1]);
        float2 f2 = unpk(acc[2]), f3 = unpk(acc[3]);
        XA[0 * 256 + q] = f0.x + b;  XA[1 * 256 + q] = f0.y + b;
        XA[2 * 256 + q] = f1.x + b;  XA[3 * 256 + q] = f1.y + b;
        XA[4 * 256 + q] = f2.x + b;  XA[5 * 256 + q] = f2.y + b;
        XA[6 * 256 + q] = f3.x + b;  XA[7 * 256 + q] = f3.y + b;
    }
    __syncthreads();

    // ---- Phase F: fts_X = X2(16x16) @ FC(16x96), in place in FC ----
    {
        const int i = t >> 5, lane = t & 31;
        const float* X2 = &XA[i * 256];
#pragma unroll
        for (int u = 0; u < 3; u++) {
            int c = lane + 32 * u;
            float f[16];
#pragma unroll
            for (int cc = 0; cc < 16; cc++) f[cc] = FC[(i * 16 + cc) * FCS + c];
#pragma unroll
            for (int r = 0; r < 16; r++) {
                float acc = 0.f;
                const float4* xr = (const float4*)&X2[r * 16];
#pragma unroll
                for (int c4 = 0; c4 < 4; c4++) {
                    float4 xv = xr[c4];
                    acc += xv.x * f[c4 * 4] + xv.y * f[c4 * 4 + 1]
                         + xv.z * f[c4 * 4 + 2] + xv.w * f[c4 * 4 + 3];
                }
                FC[(i * 16 + r) * FCS + c] = acc;
            }
        }
    }
    __syncthreads();

    // ---- Phase G1: depthwise dw[cm] = sum_k ftsX[k][c]*dwW[c][m][k] + dwb ----
    float* DWS = XB;   // reuse as [8][256], first 192 valid
    {
        const int i = t >> 5, lane = t & 31;
#pragma unroll
        for (int u = 0; u < 6; u++) {
            int cm = lane + 32 * u;         // 0..191
            int c = cm >> 1, m = cm & 1;
            float w[16];
            const float4* wp = (const float4*)(dwW + c * 32 + m * 16);
            *(float4*)&w[0]  = wp[0]; *(float4*)&w[4]  = wp[1];
            *(float4*)&w[8]  = wp[2]; *(float4*)&w[12] = wp[3];
            float acc = dwb[cm];
#pragma unroll
            for (int k = 0; k < 16; k++) acc += FC[(i * 16 + k) * FCS + c] * w[k];
            DWS[i * 256 + cm] = acc;
        }
    }
    __syncthreads();

    // ---- Phase G2: out = end_g*(elu(dw @ pwW + pwb)*BNI) + end_be ----
    {
        const int i = t >> 5, lane = t & 31;
        const int ob = lane * 4;
        ulonglong2 bi = *(const ulonglong2*)&pwb[ob];
        u64 acc0 = bi.x, acc1 = bi.y;
        const float* pwp = pwW + ob;
#pragma unroll 1
        for (int jt = 0; jt < 192; jt += 4) {
            ulonglong2 w[4];
#pragma unroll
            for (int u = 0; u < 4; u++)
                w[u] = *(const ulonglong2*)&pwp[(jt + u) * 128];
#pragma unroll
            for (int u = 0; u < 4; u++) {
                u64 vd = dup2(DWS[i * 256 + jt + u]);
                acc0 = fma2(vd, w[u].x, acc0);
                acc1 = fma2(vd, w[u].y, acc1);
            }
        }
        float2 f0 = unpk(acc0), f1 = unpk(acc1);
        float4 g4 = *(const float4*)&endg[ob];
        float4 e4 = *(const float4*)&endbe[ob];
        float4 o;
        o.x = g4.x * (eluf(f0.x) * BNI) + e4.x;
        o.y = g4.y * (eluf(f0.y) * BNI) + e4.y;
        o.z = g4.z * (eluf(f1.x) * BNI) + e4.z;
        o.w = g4.w * (eluf(f1.y) * BNI) + e4.w;
        *(float4*)&out[(size_t)(gp0 + i) * 128 + ob] = o;
    }
}

// ============================================================================
extern "C" void kernel_launch(void* const* d_in, const int* in_sizes, int n_in,
                              void* d_out, int out_size)
{
    const float* rep_pts = (const float*)d_in[0];
    const float* pts     = (const float*)d_in[1];
    const float* fts     = (const float*)d_in[2];
    const int*   pts_idx = (const int*)d_in[3];
    const float* d0W  = (const float*)d_in[4];
    const float* d0b  = (const float*)d_in[5];
    const float* d0g  = (const float*)d_in[6];
    const float* d0be = (const float*)d_in[7];
    const float* d1W  = (const float*)d_in[8];
    const float* d1b  = (const float*)d_in[9];
    const float* d1g  = (const float*)d_in[10];
    const float* d1be = (const float*)d_in[11];
    const float* d2W  = (const float*)d_in[12];
    const float* d2b  = (const float*)d_in[13];
    const float* d2g  = (const float*)d_in[14];
    const float* d2be = (const float*)d_in[15];
    const float* xcW  = (const float*)d_in[16];
    const float* xcb  = (const float*)d_in[17];
    const float* xd1W = (const float*)d_in[18];
    const float* xd1b = (const float*)d_in[19];
    const float* xd2W = (const float*)d_in[20];
    const float* xd2b = (const float*)d_in[21];
    const float* dwW  = (const float*)d_in[22];
    const float* dwb  = (const float*)d_in[23];
    const float* pwW  = (const float*)d_in[24];
    const float* pwb  = (const float*)d_in[25];
    const float* endg = (const float*)d_in[26];
    const float* endbe= (const float*)d_in[27];
    float* out = (float*)d_out;

    dense0_kernel<<<4096, 256>>>(fts, d0W, d0b, d0g, d0be);

    cudaFuncSetAttribute(xconv_kernel,
                         cudaFuncAttributeMaxDynamicSharedMemorySize, SMEM_B);
    xconv_kernel<<<32768 / TILEP, 256, SMEM_B>>>(
        rep_pts, pts, pts_idx,
        d1W, d1b, d1g, d1be, d2W, d2b, d2g, d2be,
        xcW, xcb, xd1W, xd1b, xd2W, xd2b,
        dwW, dwb, pwW, pwb, endg, endbe, out);
}